// round 1
// baseline (speedup 1.0000x reference)
#include <cuda_runtime.h>
#include <math.h>

// Problem constants
#define BSZ   2
#define TSEQ  2048
#define NH    16
#define HD    64
#define CDIM  1024
#define N3    (3 * CDIM)
#define MROWS (BSZ * TSEQ)          // 4096

// Scratch (device globals: allocation-free per harness rules)
__device__ float g_q[(size_t)BSZ * NH * TSEQ * HD];
__device__ float g_k[(size_t)BSZ * NH * TSEQ * HD];
__device__ float g_v[(size_t)BSZ * NH * TSEQ * HD];
__device__ float g_y[(size_t)BSZ * TSEQ * CDIM];

// ---------------------------------------------------------------------------
// Kernel 1: QKV = X @ W_attn + b_attn, scattered into [B,H,T,D] q/k/v buffers
// 128x128x16 tile, 256 threads, 8x8 microtile
// ---------------------------------------------------------------------------
__global__ __launch_bounds__(256) void qkv_gemm_kernel(
    const float* __restrict__ X, const float* __restrict__ W,
    const float* __restrict__ bias)
{
    __shared__ float As[16][128];   // [k][m]
    __shared__ float Bs[16][128];   // [k][n]

    const int tid = threadIdx.x;
    const int tx = tid & 15;
    const int ty = tid >> 4;
    const int m0 = blockIdx.y * 128;
    const int n0 = blockIdx.x * 128;

    const int ar = tid >> 1;          // 0..127 (row within tile)
    const int ak = (tid & 1) * 8;     // 0 or 8
    const int bk = tid >> 4;          // 0..15
    const int bn = (tid & 15) * 8;    // 0..120

    float acc[8][8];
#pragma unroll
    for (int i = 0; i < 8; i++)
#pragma unroll
        for (int j = 0; j < 8; j++) acc[i][j] = 0.f;

    const float* Aptr = X + (size_t)(m0 + ar) * CDIM + ak;

    for (int k0 = 0; k0 < CDIM; k0 += 16) {
        float4 a0 = *(const float4*)(Aptr + k0);
        float4 a1 = *(const float4*)(Aptr + k0 + 4);
        float4 b0 = *(const float4*)(W + (size_t)(k0 + bk) * N3 + n0 + bn);
        float4 b1 = *(const float4*)(W + (size_t)(k0 + bk) * N3 + n0 + bn + 4);
        __syncthreads();
        As[ak + 0][ar] = a0.x; As[ak + 1][ar] = a0.y;
        As[ak + 2][ar] = a0.z; As[ak + 3][ar] = a0.w;
        As[ak + 4][ar] = a1.x; As[ak + 5][ar] = a1.y;
        As[ak + 6][ar] = a1.z; As[ak + 7][ar] = a1.w;
        *(float4*)&Bs[bk][bn]     = b0;
        *(float4*)&Bs[bk][bn + 4] = b1;
        __syncthreads();
#pragma unroll
        for (int k = 0; k < 16; k++) {
            float a[8], b[8];
            *(float4*)(a)     = *(const float4*)&As[k][ty * 8];
            *(float4*)(a + 4) = *(const float4*)&As[k][ty * 8 + 4];
            *(float4*)(b)     = *(const float4*)&Bs[k][tx * 8];
            *(float4*)(b + 4) = *(const float4*)&Bs[k][tx * 8 + 4];
#pragma unroll
            for (int i = 0; i < 8; i++)
#pragma unroll
                for (int j = 0; j < 8; j++) acc[i][j] += a[i] * b[j];
        }
    }

    // epilogue: add bias, scatter into q/k/v [B,H,T,D]
    const int n_base = n0 + tx * 8;           // 8 consecutive cols, same (sec,h)
    float bv[8];
#pragma unroll
    for (int j = 0; j < 8; j++) bv[j] = bias[n_base + j];

    const int sec = n_base >> 10;             // 0=q 1=k 2=v
    const int c   = n_base & (CDIM - 1);
    const int h   = c >> 6;
    const int d0  = c & (HD - 1);
    float* dst = (sec == 0) ? g_q : ((sec == 1) ? g_k : g_v);

#pragma unroll
    for (int i = 0; i < 8; i++) {
        const int row = m0 + ty * 8 + i;      // b*T + t
        const int b = row >> 11;
        const int t = row & (TSEQ - 1);
        float* p = dst + (((size_t)b * NH + h) * TSEQ + t) * HD + d0;
        float4 v0 = make_float4(acc[i][0] + bv[0], acc[i][1] + bv[1],
                                acc[i][2] + bv[2], acc[i][3] + bv[3]);
        float4 v1 = make_float4(acc[i][4] + bv[4], acc[i][5] + bv[5],
                                acc[i][6] + bv[6], acc[i][7] + bv[7]);
        *(float4*)(p)     = v0;
        *(float4*)(p + 4) = v1;
    }
}

// ---------------------------------------------------------------------------
// Kernel 2: causal flash attention. One block per (b*h, q-tile of 64).
// 256 threads; S tile 64x64 (4x4 microtile), online softmax, O accum in regs.
// ---------------------------------------------------------------------------
#define ATT_SMEM_FLOATS (3 * 64 * 65 + 64 * 64 + 64 * 16 + 3 * 64)

__global__ __launch_bounds__(256) void attn_kernel()
{
    extern __shared__ float sm[];
    float* Qs   = sm;                    // [64][65]
    float* Ks   = Qs + 64 * 65;          // [64][65]
    float* Ps   = Ks + 64 * 65;          // [64][65]
    float* Vs   = Ps + 64 * 65;          // [64][64]
    float* red  = Vs + 64 * 64;          // [64][16]
    float* mrow = red + 64 * 16;         // [64]
    float* lrow = mrow + 64;             // [64]
    float* srow = lrow + 64;             // [64]

    const int tid = threadIdx.x;
    const int tx = tid & 15;
    const int ty = tid >> 4;
    const int qi = blockIdx.x;           // q-tile index 0..31
    const int bh = blockIdx.y;           // 0..31

    const size_t head_off = (size_t)bh * TSEQ * HD;
    const float* Qg = g_q + head_off;
    const float* Kg = g_k + head_off;
    const float* Vg = g_v + head_off;

    // Load Q tile into Qs (pitch 65)
    {
        const int r  = tid >> 2;
        const int dd = (tid & 3) * 16;
        const float* src = Qg + (size_t)(qi * 64 + r) * HD + dd;
#pragma unroll
        for (int u = 0; u < 4; u++) {
            float4 v = *(const float4*)(src + u * 4);
            float* q = Qs + r * 65 + dd + u * 4;
            q[0] = v.x; q[1] = v.y; q[2] = v.z; q[3] = v.w;
        }
    }
    if (tid < 64) { mrow[tid] = -INFINITY; lrow[tid] = 0.f; }

    float o[4][4];
#pragma unroll
    for (int i = 0; i < 4; i++)
#pragma unroll
        for (int j = 0; j < 4; j++) o[i][j] = 0.f;

    for (int kt = 0; kt <= qi; kt++) {
        __syncthreads();                                   // S1
        {
            const int r  = tid >> 2;
            const int dd = (tid & 3) * 16;
            const float* ksrc = Kg + (size_t)(kt * 64 + r) * HD + dd;
            const float* vsrc = Vg + (size_t)(kt * 64 + r) * HD + dd;
#pragma unroll
            for (int u = 0; u < 4; u++) {
                float4 kv = *(const float4*)(ksrc + u * 4);
                float* kq = Ks + r * 65 + dd + u * 4;
                kq[0] = kv.x; kq[1] = kv.y; kq[2] = kv.z; kq[3] = kv.w;
                *(float4*)&Vs[r * 64 + dd + u * 4] = *(const float4*)(vsrc + u * 4);
            }
        }
        __syncthreads();                                   // S2

        // S = Q K^T
        float s[4][4];
#pragma unroll
        for (int i = 0; i < 4; i++)
#pragma unroll
            for (int j = 0; j < 4; j++) s[i][j] = 0.f;

#pragma unroll 8
        for (int d = 0; d < 64; d++) {
            float qv[4], kv[4];
#pragma unroll
            for (int i = 0; i < 4; i++) qv[i] = Qs[(ty * 4 + i) * 65 + d];
#pragma unroll
            for (int j = 0; j < 4; j++) kv[j] = Ks[(tx * 4 + j) * 65 + d];
#pragma unroll
            for (int i = 0; i < 4; i++)
#pragma unroll
                for (int j = 0; j < 4; j++) s[i][j] += qv[i] * kv[j];
        }

        const bool diag = (kt == qi);
#pragma unroll
        for (int i = 0; i < 4; i++) {
            float lm = -INFINITY;
#pragma unroll
            for (int j = 0; j < 4; j++) {
                s[i][j] *= 0.125f;
                if (diag && (tx * 4 + j) > (ty * 4 + i)) s[i][j] = -INFINITY;
                lm = fmaxf(lm, s[i][j]);
            }
            red[(ty * 4 + i) * 16 + tx] = lm;
        }
        __syncthreads();                                   // S3

        if (tid < 64) {
            float rm = red[tid * 16];
#pragma unroll
            for (int u = 1; u < 16; u++) rm = fmaxf(rm, red[tid * 16 + u]);
            const float mold = mrow[tid];
            const float mnew = fmaxf(mold, rm);
            srow[tid] = __expf(mold - mnew);
            mrow[tid] = mnew;
        }
        __syncthreads();                                   // S4

#pragma unroll
        for (int i = 0; i < 4; i++) {
            const float mi = mrow[ty * 4 + i];
            const float sc = srow[ty * 4 + i];
            float rs = 0.f;
#pragma unroll
            for (int j = 0; j < 4; j++) {
                const float p = __expf(s[i][j] - mi);
                Ps[(ty * 4 + i) * 65 + tx * 4 + j] = p;
                rs += p;
                o[i][j] *= sc;
            }
            red[(ty * 4 + i) * 16 + tx] = rs;
        }
        __syncthreads();                                   // S5

        if (tid < 64) {
            float rs = 0.f;
#pragma unroll
            for (int u = 0; u < 16; u++) rs += red[tid * 16 + u];
            lrow[tid] = lrow[tid] * srow[tid] + rs;
        }

        // O += P @ V
#pragma unroll 8
        for (int k = 0; k < 64; k++) {
            float pv[4];
#pragma unroll
            for (int i = 0; i < 4; i++) pv[i] = Ps[(ty * 4 + i) * 65 + k];
            float4 v4 = *(const float4*)&Vs[k * 64 + tx * 4];
#pragma unroll
            for (int i = 0; i < 4; i++) {
                o[i][0] += pv[i] * v4.x;
                o[i][1] += pv[i] * v4.y;
                o[i][2] += pv[i] * v4.z;
                o[i][3] += pv[i] * v4.w;
            }
        }
    }
    __syncthreads();

    const int b = bh >> 4;
    const int h = bh & 15;
#pragma unroll
    for (int i = 0; i < 4; i++) {
        const int r = ty * 4 + i;
        const float inv = 1.0f / lrow[r];
        const int t = qi * 64 + r;
        float4 v = make_float4(o[i][0] * inv, o[i][1] * inv,
                               o[i][2] * inv, o[i][3] * inv);
        *(float4*)&g_y[((size_t)b * TSEQ + t) * CDIM + h * 64 + tx * 4] = v;
    }
}

// ---------------------------------------------------------------------------
// Kernel 3: out = Y @ W_proj + b_proj, [4096,1024] = [4096,1024]x[1024,1024]
// ---------------------------------------------------------------------------
__global__ __launch_bounds__(256) void proj_gemm_kernel(
    const float* __restrict__ W, const float* __restrict__ bias,
    float* __restrict__ out)
{
    __shared__ float As[16][128];
    __shared__ float Bs[16][128];

    const int tid = threadIdx.x;
    const int tx = tid & 15;
    const int ty = tid >> 4;
    const int m0 = blockIdx.y * 128;
    const int n0 = blockIdx.x * 128;

    const int ar = tid >> 1;
    const int ak = (tid & 1) * 8;
    const int bk = tid >> 4;
    const int bn = (tid & 15) * 8;

    float acc[8][8];
#pragma unroll
    for (int i = 0; i < 8; i++)
#pragma unroll
        for (int j = 0; j < 8; j++) acc[i][j] = 0.f;

    const float* Aptr = g_y + (size_t)(m0 + ar) * CDIM + ak;

    for (int k0 = 0; k0 < CDIM; k0 += 16) {
        float4 a0 = *(const float4*)(Aptr + k0);
        float4 a1 = *(const float4*)(Aptr + k0 + 4);
        float4 b0 = *(const float4*)(W + (size_t)(k0 + bk) * CDIM + n0 + bn);
        float4 b1 = *(const float4*)(W + (size_t)(k0 + bk) * CDIM + n0 + bn + 4);
        __syncthreads();
        As[ak + 0][ar] = a0.x; As[ak + 1][ar] = a0.y;
        As[ak + 2][ar] = a0.z; As[ak + 3][ar] = a0.w;
        As[ak + 4][ar] = a1.x; As[ak + 5][ar] = a1.y;
        As[ak + 6][ar] = a1.z; As[ak + 7][ar] = a1.w;
        *(float4*)&Bs[bk][bn]     = b0;
        *(float4*)&Bs[bk][bn + 4] = b1;
        __syncthreads();
#pragma unroll
        for (int k = 0; k < 16; k++) {
            float a[8], b[8];
            *(float4*)(a)     = *(const float4*)&As[k][ty * 8];
            *(float4*)(a + 4) = *(const float4*)&As[k][ty * 8 + 4];
            *(float4*)(b)     = *(const float4*)&Bs[k][tx * 8];
            *(float4*)(b + 4) = *(const float4*)&Bs[k][tx * 8 + 4];
#pragma unroll
            for (int i = 0; i < 8; i++)
#pragma unroll
                for (int j = 0; j < 8; j++) acc[i][j] += a[i] * b[j];
        }
    }

    const int n_base = n0 + tx * 8;
    float bv[8];
#pragma unroll
    for (int j = 0; j < 8; j++) bv[j] = bias[n_base + j];

#pragma unroll
    for (int i = 0; i < 8; i++) {
        const int row = m0 + ty * 8 + i;
        float* p = out + (size_t)row * CDIM + n_base;
        float4 v0 = make_float4(acc[i][0] + bv[0], acc[i][1] + bv[1],
                                acc[i][2] + bv[2], acc[i][3] + bv[3]);
        float4 v1 = make_float4(acc[i][4] + bv[4], acc[i][5] + bv[5],
                                acc[i][6] + bv[6], acc[i][7] + bv[7]);
        *(float4*)(p)     = v0;
        *(float4*)(p + 4) = v1;
    }
}

// ---------------------------------------------------------------------------
extern "C" void kernel_launch(void* const* d_in, const int* in_sizes, int n_in,
                              void* d_out, int out_size)
{
    const float* x      = (const float*)d_in[0];
    const float* W_attn = (const float*)d_in[1];
    const float* b_attn = (const float*)d_in[2];
    const float* W_proj = (const float*)d_in[3];
    const float* b_proj = (const float*)d_in[4];
    float* out = (float*)d_out;

    static bool attr_set = false;
    const int att_smem = ATT_SMEM_FLOATS * (int)sizeof(float);
    if (!attr_set) {
        cudaFuncSetAttribute(attn_kernel,
                             cudaFuncAttributeMaxDynamicSharedMemorySize,
                             att_smem);
        attr_set = true;
    }

    // 1) QKV GEMM: [4096,1024] x [1024,3072]
    {
        dim3 grid(N3 / 128, MROWS / 128);
        qkv_gemm_kernel<<<grid, 256>>>(x, W_attn, b_attn);
    }
    // 2) Flash attention
    {
        dim3 grid(TSEQ / 64, BSZ * NH);
        attn_kernel<<<grid, 256, att_smem>>>();
    }
    // 3) Projection GEMM: [4096,1024] x [1024,1024]
    {
        dim3 grid(CDIM / 128, MROWS / 128);
        proj_gemm_kernel<<<grid, 256>>>(W_proj, b_proj, out);
    }
}

// round 4
// speedup vs baseline: 2.3807x; 2.3807x over previous
#include <cuda_runtime.h>
#include <math.h>
#include <stdint.h>

// Problem constants
#define BSZ   2
#define TSEQ  2048
#define NH    16
#define HD    64
#define CDIM  1024
#define N3    (3 * CDIM)
#define MROWS (BSZ * TSEQ)          // 4096

// Scratch (device globals: allocation-free per harness rules)
__device__ float g_q[(size_t)BSZ * NH * TSEQ * HD];
__device__ float g_k[(size_t)BSZ * NH * TSEQ * HD];
__device__ float g_v[(size_t)BSZ * NH * TSEQ * HD];
__device__ float g_y[(size_t)BSZ * TSEQ * CDIM];

// ---------------------------------------------------------------------------
// tf32 helpers (portable PTX, sm_80+)
// ---------------------------------------------------------------------------
__device__ __forceinline__ uint32_t f2tf32(float x) {
    uint32_t u;
    asm("cvt.rn.tf32.f32 %0, %1;" : "=r"(u) : "f"(x));
    return u;
}

__device__ __forceinline__ void mma_tf32(float* d, const uint32_t* a, const uint32_t* b) {
    asm volatile(
        "mma.sync.aligned.m16n8k8.row.col.f32.tf32.tf32.f32 "
        "{%0,%1,%2,%3}, {%4,%5,%6,%7}, {%8,%9}, {%0,%1,%2,%3};"
        : "+f"(d[0]), "+f"(d[1]), "+f"(d[2]), "+f"(d[3])
        : "r"(a[0]), "r"(a[1]), "r"(a[2]), "r"(a[3]), "r"(b[0]), "r"(b[1]));
}

// ---------------------------------------------------------------------------
// tf32 mma.sync GEMM: C[4096-tileM, ldb-tileN] = A[M,1024] @ W[1024,ldb] + bias
// 256 threads, 128x128 tile, K-tile 32, double-buffered smem.
// A smem: [128][36] (m-major, pad 4 -> conflict-free frag LDS)
// B smem: [32][132] (k-major, pad 4 -> <=2-way frag LDS, conflict-free fill)
// A_GY: read A operand from device-global g_y (can't pass __device__ symbol
//       from host).  EPI_QKV: scatter epilogue into g_q/g_k/g_v.
// ---------------------------------------------------------------------------
#define KTILE     32
#define NCHUNK    (CDIM / KTILE)           // 32
#define APITCH    36
#define BPITCH    132
#define A_FLOATS  (128 * APITCH)           // 4608
#define STAGE_FLOATS (128 * APITCH + KTILE * BPITCH)  // 8832
#define GEMM_DYN  (2 * STAGE_FLOATS * 4)   // 70656 bytes

template <bool EPI_QKV, bool A_GY>
__global__ __launch_bounds__(256)
void tc_gemm_kernel(const float* __restrict__ Ain, const float* __restrict__ W,
                    const float* __restrict__ bias, float* __restrict__ out,
                    int ldb)
{
    extern __shared__ __align__(16) float sm[];
    __shared__ float sbias[128];

    const float* __restrict__ A = A_GY ? (const float*)g_y : Ain;

    const int tid    = threadIdx.x;
    const int lane   = tid & 31;
    const int wid    = tid >> 5;
    const int warp_m = wid & 1;            // 0..1 (64 rows each)
    const int warp_n = wid >> 1;           // 0..3 (32 cols each)
    const int m0 = blockIdx.y * 128;
    const int n0 = blockIdx.x * 128;

    if (tid < 128) sbias[tid] = bias[n0 + tid];

    float acc[4][4][4];
#pragma unroll
    for (int mf = 0; mf < 4; mf++)
#pragma unroll
        for (int nf = 0; nf < 4; nf++)
#pragma unroll
            for (int r = 0; r < 4; r++) acc[mf][nf][r] = 0.f;

    // ---- prologue: fill stage 0 ----
    {
        float* As = sm;
        float* Bs = sm + A_FLOATS;
#pragma unroll
        for (int u = 0; u < 4; u++) {
            const int idx = tid + u * 256;
            const int row = idx >> 3, c4 = idx & 7;
            float4 v = *(const float4*)(A + (size_t)(m0 + row) * CDIM + c4 * 4);
            uint4 t = make_uint4(f2tf32(v.x), f2tf32(v.y), f2tf32(v.z), f2tf32(v.w));
            *(uint4*)(As + row * APITCH + c4 * 4) = t;
        }
#pragma unroll
        for (int u = 0; u < 4; u++) {
            const int idx = tid + u * 256;
            const int k = idx >> 5, n4 = idx & 31;
            float4 v = *(const float4*)(W + (size_t)k * ldb + n0 + n4 * 4);
            uint4 t = make_uint4(f2tf32(v.x), f2tf32(v.y), f2tf32(v.z), f2tf32(v.w));
            *(uint4*)(Bs + k * BPITCH + n4 * 4) = t;
        }
    }
    __syncthreads();

    for (int i = 0; i < NCHUNK; i++) {
        // prefetch next K-tile into registers
        float4 pa[4], pb[4];
        if (i + 1 < NCHUNK) {
            const int k0n = (i + 1) * KTILE;
#pragma unroll
            for (int u = 0; u < 4; u++) {
                const int idx = tid + u * 256;
                const int row = idx >> 3, c4 = idx & 7;
                pa[u] = *(const float4*)(A + (size_t)(m0 + row) * CDIM + k0n + c4 * 4);
            }
#pragma unroll
            for (int u = 0; u < 4; u++) {
                const int idx = tid + u * 256;
                const int k = idx >> 5, n4 = idx & 31;
                pb[u] = *(const float4*)(W + (size_t)(k0n + k) * ldb + n0 + n4 * 4);
            }
        }

        // compute on current stage
        {
            const uint32_t* As = (const uint32_t*)(sm + (i & 1) * STAGE_FLOATS);
            const uint32_t* Bs = As + A_FLOATS;
#pragma unroll
            for (int kk = 0; kk < KTILE; kk += 8) {
                uint32_t a[4][4], b[4][2];
                const int ka = kk + (lane & 3);
#pragma unroll
                for (int mf = 0; mf < 4; mf++) {
                    const int m = warp_m * 64 + mf * 16 + (lane >> 2);
                    a[mf][0] = As[m * APITCH + ka];
                    a[mf][1] = As[(m + 8) * APITCH + ka];
                    a[mf][2] = As[m * APITCH + ka + 4];
                    a[mf][3] = As[(m + 8) * APITCH + ka + 4];
                }
#pragma unroll
                for (int nf = 0; nf < 4; nf++) {
                    const int n = warp_n * 32 + nf * 8 + (lane >> 2);
                    b[nf][0] = Bs[ka * BPITCH + n];
                    b[nf][1] = Bs[(ka + 4) * BPITCH + n];
                }
#pragma unroll
                for (int mf = 0; mf < 4; mf++)
#pragma unroll
                    for (int nf = 0; nf < 4; nf++)
                        mma_tf32(acc[mf][nf], a[mf], b[nf]);
            }
        }

        // store prefetched tile into other stage
        if (i + 1 < NCHUNK) {
            float* As = sm + ((i + 1) & 1) * STAGE_FLOATS;
            float* Bs = As + A_FLOATS;
#pragma unroll
            for (int u = 0; u < 4; u++) {
                const int idx = tid + u * 256;
                const int row = idx >> 3, c4 = idx & 7;
                uint4 t = make_uint4(f2tf32(pa[u].x), f2tf32(pa[u].y),
                                     f2tf32(pa[u].z), f2tf32(pa[u].w));
                *(uint4*)(As + row * APITCH + c4 * 4) = t;
            }
#pragma unroll
            for (int u = 0; u < 4; u++) {
                const int idx = tid + u * 256;
                const int k = idx >> 5, n4 = idx & 31;
                uint4 t = make_uint4(f2tf32(pb[u].x), f2tf32(pb[u].y),
                                     f2tf32(pb[u].z), f2tf32(pb[u].w));
                *(uint4*)(Bs + k * BPITCH + n4 * 4) = t;
            }
        }
        __syncthreads();
    }

    // ---- epilogue: direct STG.64 from fragments (+bias) ----
#pragma unroll
    for (int mf = 0; mf < 4; mf++) {
        const int r0 = m0 + warp_m * 64 + mf * 16 + (lane >> 2);
#pragma unroll
        for (int nf = 0; nf < 4; nf++) {
            const int cb_loc = warp_n * 32 + nf * 8 + 2 * (lane & 3);  // 0..127
            const float b0 = sbias[cb_loc], b1 = sbias[cb_loc + 1];
            float2 v0 = make_float2(acc[mf][nf][0] + b0, acc[mf][nf][1] + b1);
            float2 v1 = make_float2(acc[mf][nf][2] + b0, acc[mf][nf][3] + b1);
            if (EPI_QKV) {
                const int col = n0 + cb_loc;
                const int sec = col >> 10;
                const int c   = col & (CDIM - 1);
                const int h   = c >> 6;
                const int d0  = c & (HD - 1);
                float* dst = (sec == 0) ? g_q : ((sec == 1) ? g_k : g_v);
                const int bb0 = r0 >> 11, t0 = r0 & (TSEQ - 1);
                *(float2*)(dst + (((size_t)bb0 * NH + h) * TSEQ + t0) * HD + d0) = v0;
                const int r1 = r0 + 8;
                const int bb1 = r1 >> 11, t1 = r1 & (TSEQ - 1);
                *(float2*)(dst + (((size_t)bb1 * NH + h) * TSEQ + t1) * HD + d0) = v1;
            } else {
                *(float2*)(out + (size_t)r0 * CDIM + n0 + cb_loc) = v0;
                *(float2*)(out + (size_t)(r0 + 8) * CDIM + n0 + cb_loc) = v1;
            }
        }
    }
}

// ---------------------------------------------------------------------------
// Kernel 2: causal flash attention (fp32 SIMT, unchanged from R1)
// ---------------------------------------------------------------------------
#define ATT_SMEM_FLOATS (3 * 64 * 65 + 64 * 64 + 64 * 16 + 3 * 64)

__global__ __launch_bounds__(256) void attn_kernel()
{
    extern __shared__ float sm[];
    float* Qs   = sm;
    float* Ks   = Qs + 64 * 65;
    float* Ps   = Ks + 64 * 65;
    float* Vs   = Ps + 64 * 65;
    float* red  = Vs + 64 * 64;
    float* mrow = red + 64 * 16;
    float* lrow = mrow + 64;
    float* srow = lrow + 64;

    const int tid = threadIdx.x;
    const int tx = tid & 15;
    const int ty = tid >> 4;
    const int qi = blockIdx.x;
    const int bh = blockIdx.y;

    const size_t head_off = (size_t)bh * TSEQ * HD;
    const float* Qg = g_q + head_off;
    const float* Kg = g_k + head_off;
    const float* Vg = g_v + head_off;

    {
        const int r  = tid >> 2;
        const int dd = (tid & 3) * 16;
        const float* src = Qg + (size_t)(qi * 64 + r) * HD + dd;
#pragma unroll
        for (int u = 0; u < 4; u++) {
            float4 v = *(const float4*)(src + u * 4);
            float* q = Qs + r * 65 + dd + u * 4;
            q[0] = v.x; q[1] = v.y; q[2] = v.z; q[3] = v.w;
        }
    }
    if (tid < 64) { mrow[tid] = -INFINITY; lrow[tid] = 0.f; }

    float o[4][4];
#pragma unroll
    for (int i = 0; i < 4; i++)
#pragma unroll
        for (int j = 0; j < 4; j++) o[i][j] = 0.f;

    for (int kt = 0; kt <= qi; kt++) {
        __syncthreads();
        {
            const int r  = tid >> 2;
            const int dd = (tid & 3) * 16;
            const float* ksrc = Kg + (size_t)(kt * 64 + r) * HD + dd;
            const float* vsrc = Vg + (size_t)(kt * 64 + r) * HD + dd;
#pragma unroll
            for (int u = 0; u < 4; u++) {
                float4 kv = *(const float4*)(ksrc + u * 4);
                float* kq = Ks + r * 65 + dd + u * 4;
                kq[0] = kv.x; kq[1] = kv.y; kq[2] = kv.z; kq[3] = kv.w;
                *(float4*)&Vs[r * 64 + dd + u * 4] = *(const float4*)(vsrc + u * 4);
            }
        }
        __syncthreads();

        float s[4][4];
#pragma unroll
        for (int i = 0; i < 4; i++)
#pragma unroll
            for (int j = 0; j < 4; j++) s[i][j] = 0.f;

#pragma unroll 8
        for (int d = 0; d < 64; d++) {
            float qv[4], kv[4];
#pragma unroll
            for (int i = 0; i < 4; i++) qv[i] = Qs[(ty * 4 + i) * 65 + d];
#pragma unroll
            for (int j = 0; j < 4; j++) kv[j] = Ks[(tx * 4 + j) * 65 + d];
#pragma unroll
            for (int i = 0; i < 4; i++)
#pragma unroll
                for (int j = 0; j < 4; j++) s[i][j] += qv[i] * kv[j];
        }

        const bool diag = (kt == qi);
#pragma unroll
        for (int i = 0; i < 4; i++) {
            float lm = -INFINITY;
#pragma unroll
            for (int j = 0; j < 4; j++) {
                s[i][j] *= 0.125f;
                if (diag && (tx * 4 + j) > (ty * 4 + i)) s[i][j] = -INFINITY;
                lm = fmaxf(lm, s[i][j]);
            }
            red[(ty * 4 + i) * 16 + tx] = lm;
        }
        __syncthreads();

        if (tid < 64) {
            float rm = red[tid * 16];
#pragma unroll
            for (int u = 1; u < 16; u++) rm = fmaxf(rm, red[tid * 16 + u]);
            const float mold = mrow[tid];
            const float mnew = fmaxf(mold, rm);
            srow[tid] = __expf(mold - mnew);
            mrow[tid] = mnew;
        }
        __syncthreads();

#pragma unroll
        for (int i = 0; i < 4; i++) {
            const float mi = mrow[ty * 4 + i];
            const float sc = srow[ty * 4 + i];
            float rs = 0.f;
#pragma unroll
            for (int j = 0; j < 4; j++) {
                const float p = __expf(s[i][j] - mi);
                Ps[(ty * 4 + i) * 65 + tx * 4 + j] = p;
                rs += p;
                o[i][j] *= sc;
            }
            red[(ty * 4 + i) * 16 + tx] = rs;
        }
        __syncthreads();

        if (tid < 64) {
            float rs = 0.f;
#pragma unroll
            for (int u = 0; u < 16; u++) rs += red[tid * 16 + u];
            lrow[tid] = lrow[tid] * srow[tid] + rs;
        }

#pragma unroll 8
        for (int k = 0; k < 64; k++) {
            float pv[4];
#pragma unroll
            for (int i = 0; i < 4; i++) pv[i] = Ps[(ty * 4 + i) * 65 + k];
            float4 v4 = *(const float4*)&Vs[k * 64 + tx * 4];
#pragma unroll
            for (int i = 0; i < 4; i++) {
                o[i][0] += pv[i] * v4.x;
                o[i][1] += pv[i] * v4.y;
                o[i][2] += pv[i] * v4.z;
                o[i][3] += pv[i] * v4.w;
            }
        }
    }
    __syncthreads();

    const int b = bh >> 4;
    const int h = bh & 15;
#pragma unroll
    for (int i = 0; i < 4; i++) {
        const int r = ty * 4 + i;
        const float inv = 1.0f / lrow[r];
        const int t = qi * 64 + r;
        float4 v = make_float4(o[i][0] * inv, o[i][1] * inv,
                               o[i][2] * inv, o[i][3] * inv);
        *(float4*)&g_y[((size_t)b * TSEQ + t) * CDIM + h * 64 + tx * 4] = v;
    }
}

// ---------------------------------------------------------------------------
extern "C" void kernel_launch(void* const* d_in, const int* in_sizes, int n_in,
                              void* d_out, int out_size)
{
    const float* x      = (const float*)d_in[0];
    const float* W_attn = (const float*)d_in[1];
    const float* b_attn = (const float*)d_in[2];
    const float* W_proj = (const float*)d_in[3];
    const float* b_proj = (const float*)d_in[4];
    float* out = (float*)d_out;

    static bool attr_set = false;
    const int att_smem = ATT_SMEM_FLOATS * (int)sizeof(float);
    if (!attr_set) {
        cudaFuncSetAttribute(attn_kernel,
                             cudaFuncAttributeMaxDynamicSharedMemorySize, att_smem);
        cudaFuncSetAttribute((const void*)tc_gemm_kernel<true, false>,
                             cudaFuncAttributeMaxDynamicSharedMemorySize, GEMM_DYN);
        cudaFuncSetAttribute((const void*)tc_gemm_kernel<false, true>,
                             cudaFuncAttributeMaxDynamicSharedMemorySize, GEMM_DYN);
        attr_set = true;
    }

    // 1) QKV GEMM (tf32 mma.sync): [4096,1024] x [1024,3072] -> g_q/g_k/g_v
    {
        dim3 grid(N3 / 128, MROWS / 128);
        tc_gemm_kernel<true, false><<<grid, 256, GEMM_DYN>>>(x, W_attn, b_attn, nullptr, N3);
    }
    // 2) Flash attention (fp32 SIMT)
    {
        dim3 grid(TSEQ / 64, BSZ * NH);
        attn_kernel<<<grid, 256, att_smem>>>();
    }
    // 3) Projection GEMM (tf32 mma.sync): A = g_y (device symbol, read in-kernel)
    {
        dim3 grid(CDIM / 128, MROWS / 128);
        tc_gemm_kernel<false, true><<<grid, 256, GEMM_DYN>>>(nullptr, W_proj, b_proj, out, CDIM);
    }
}

// round 5
// speedup vs baseline: 4.3596x; 1.8313x over previous
#include <cuda_runtime.h>
#include <math.h>
#include <stdint.h>

// Problem constants
#define BSZ   2
#define TSEQ  2048
#define NH    16
#define HD    64
#define CDIM  1024
#define N3    (3 * CDIM)
#define MROWS (BSZ * TSEQ)          // 4096

// Scratch (device globals: allocation-free per harness rules)
__device__ float g_q[(size_t)BSZ * NH * TSEQ * HD];
__device__ float g_k[(size_t)BSZ * NH * TSEQ * HD];
__device__ float g_v[(size_t)BSZ * NH * TSEQ * HD];
__device__ float g_y[(size_t)BSZ * TSEQ * CDIM];

// ---------------------------------------------------------------------------
// tf32 helpers (portable PTX, sm_80+)
// ---------------------------------------------------------------------------
__device__ __forceinline__ uint32_t f2tf32(float x) {
    uint32_t u;
    asm("cvt.rn.tf32.f32 %0, %1;" : "=r"(u) : "f"(x));
    return u;
}

__device__ __forceinline__ void mma_tf32(float* d, const uint32_t* a, const uint32_t* b) {
    asm volatile(
        "mma.sync.aligned.m16n8k8.row.col.f32.tf32.tf32.f32 "
        "{%0,%1,%2,%3}, {%4,%5,%6,%7}, {%8,%9}, {%0,%1,%2,%3};"
        : "+f"(d[0]), "+f"(d[1]), "+f"(d[2]), "+f"(d[3])
        : "r"(a[0]), "r"(a[1]), "r"(a[2]), "r"(a[3]), "r"(b[0]), "r"(b[1]));
}

// ---------------------------------------------------------------------------
// tf32 mma.sync GEMM (unchanged from R4)
// ---------------------------------------------------------------------------
#define KTILE     32
#define NCHUNK    (CDIM / KTILE)           // 32
#define APITCH    36
#define BPITCH    132
#define A_FLOATS  (128 * APITCH)           // 4608
#define STAGE_FLOATS (128 * APITCH + KTILE * BPITCH)  // 8832
#define GEMM_DYN  (2 * STAGE_FLOATS * 4)   // 70656 bytes

template <bool EPI_QKV, bool A_GY>
__global__ __launch_bounds__(256)
void tc_gemm_kernel(const float* __restrict__ Ain, const float* __restrict__ W,
                    const float* __restrict__ bias, float* __restrict__ out,
                    int ldb)
{
    extern __shared__ __align__(16) float sm[];
    __shared__ float sbias[128];

    const float* __restrict__ A = A_GY ? (const float*)g_y : Ain;

    const int tid    = threadIdx.x;
    const int lane   = tid & 31;
    const int wid    = tid >> 5;
    const int warp_m = wid & 1;
    const int warp_n = wid >> 1;
    const int m0 = blockIdx.y * 128;
    const int n0 = blockIdx.x * 128;

    if (tid < 128) sbias[tid] = bias[n0 + tid];

    float acc[4][4][4];
#pragma unroll
    for (int mf = 0; mf < 4; mf++)
#pragma unroll
        for (int nf = 0; nf < 4; nf++)
#pragma unroll
            for (int r = 0; r < 4; r++) acc[mf][nf][r] = 0.f;

    {
        float* As = sm;
        float* Bs = sm + A_FLOATS;
#pragma unroll
        for (int u = 0; u < 4; u++) {
            const int idx = tid + u * 256;
            const int row = idx >> 3, c4 = idx & 7;
            float4 v = *(const float4*)(A + (size_t)(m0 + row) * CDIM + c4 * 4);
            uint4 t = make_uint4(f2tf32(v.x), f2tf32(v.y), f2tf32(v.z), f2tf32(v.w));
            *(uint4*)(As + row * APITCH + c4 * 4) = t;
        }
#pragma unroll
        for (int u = 0; u < 4; u++) {
            const int idx = tid + u * 256;
            const int k = idx >> 5, n4 = idx & 31;
            float4 v = *(const float4*)(W + (size_t)k * ldb + n0 + n4 * 4);
            uint4 t = make_uint4(f2tf32(v.x), f2tf32(v.y), f2tf32(v.z), f2tf32(v.w));
            *(uint4*)(Bs + k * BPITCH + n4 * 4) = t;
        }
    }
    __syncthreads();

    for (int i = 0; i < NCHUNK; i++) {
        float4 pa[4], pb[4];
        if (i + 1 < NCHUNK) {
            const int k0n = (i + 1) * KTILE;
#pragma unroll
            for (int u = 0; u < 4; u++) {
                const int idx = tid + u * 256;
                const int row = idx >> 3, c4 = idx & 7;
                pa[u] = *(const float4*)(A + (size_t)(m0 + row) * CDIM + k0n + c4 * 4);
            }
#pragma unroll
            for (int u = 0; u < 4; u++) {
                const int idx = tid + u * 256;
                const int k = idx >> 5, n4 = idx & 31;
                pb[u] = *(const float4*)(W + (size_t)(k0n + k) * ldb + n0 + n4 * 4);
            }
        }

        {
            const uint32_t* As = (const uint32_t*)(sm + (i & 1) * STAGE_FLOATS);
            const uint32_t* Bs = As + A_FLOATS;
#pragma unroll
            for (int kk = 0; kk < KTILE; kk += 8) {
                uint32_t a[4][4], b[4][2];
                const int ka = kk + (lane & 3);
#pragma unroll
                for (int mf = 0; mf < 4; mf++) {
                    const int m = warp_m * 64 + mf * 16 + (lane >> 2);
                    a[mf][0] = As[m * APITCH + ka];
                    a[mf][1] = As[(m + 8) * APITCH + ka];
                    a[mf][2] = As[m * APITCH + ka + 4];
                    a[mf][3] = As[(m + 8) * APITCH + ka + 4];
                }
#pragma unroll
                for (int nf = 0; nf < 4; nf++) {
                    const int n = warp_n * 32 + nf * 8 + (lane >> 2);
                    b[nf][0] = Bs[ka * BPITCH + n];
                    b[nf][1] = Bs[(ka + 4) * BPITCH + n];
                }
#pragma unroll
                for (int mf = 0; mf < 4; mf++)
#pragma unroll
                    for (int nf = 0; nf < 4; nf++)
                        mma_tf32(acc[mf][nf], a[mf], b[nf]);
            }
        }

        if (i + 1 < NCHUNK) {
            float* As = sm + ((i + 1) & 1) * STAGE_FLOATS;
            float* Bs = As + A_FLOATS;
#pragma unroll
            for (int u = 0; u < 4; u++) {
                const int idx = tid + u * 256;
                const int row = idx >> 3, c4 = idx & 7;
                uint4 t = make_uint4(f2tf32(pa[u].x), f2tf32(pa[u].y),
                                     f2tf32(pa[u].z), f2tf32(pa[u].w));
                *(uint4*)(As + row * APITCH + c4 * 4) = t;
            }
#pragma unroll
            for (int u = 0; u < 4; u++) {
                const int idx = tid + u * 256;
                const int k = idx >> 5, n4 = idx & 31;
                uint4 t = make_uint4(f2tf32(pb[u].x), f2tf32(pb[u].y),
                                     f2tf32(pb[u].z), f2tf32(pb[u].w));
                *(uint4*)(Bs + k * BPITCH + n4 * 4) = t;
            }
        }
        __syncthreads();
    }

#pragma unroll
    for (int mf = 0; mf < 4; mf++) {
        const int r0 = m0 + warp_m * 64 + mf * 16 + (lane >> 2);
#pragma unroll
        for (int nf = 0; nf < 4; nf++) {
            const int cb_loc = warp_n * 32 + nf * 8 + 2 * (lane & 3);
            const float b0 = sbias[cb_loc], b1 = sbias[cb_loc + 1];
            float2 v0 = make_float2(acc[mf][nf][0] + b0, acc[mf][nf][1] + b1);
            float2 v1 = make_float2(acc[mf][nf][2] + b0, acc[mf][nf][3] + b1);
            if (EPI_QKV) {
                const int col = n0 + cb_loc;
                const int sec = col >> 10;
                const int c   = col & (CDIM - 1);
                const int h   = c >> 6;
                const int d0  = c & (HD - 1);
                float* dst = (sec == 0) ? g_q : ((sec == 1) ? g_k : g_v);
                const int bb0 = r0 >> 11, t0 = r0 & (TSEQ - 1);
                *(float2*)(dst + (((size_t)bb0 * NH + h) * TSEQ + t0) * HD + d0) = v0;
                const int r1 = r0 + 8;
                const int bb1 = r1 >> 11, t1 = r1 & (TSEQ - 1);
                *(float2*)(dst + (((size_t)bb1 * NH + h) * TSEQ + t1) * HD + d0) = v1;
            } else {
                *(float2*)(out + (size_t)r0 * CDIM + n0 + cb_loc) = v0;
                *(float2*)(out + (size_t)(r0 + 8) * CDIM + n0 + cb_loc) = v1;
            }
        }
    }
}

// ---------------------------------------------------------------------------
// Kernel 2: causal flash attention on tf32 mma.sync.
// CTA: 128 q-rows x one (b,h). 8 warps x 16 rows. K-tile = 64 keys.
// Smem: Qs/Ps alias [128][68] (tf32), Ks [64][68], Vs [64][68] (natural layout).
// ---------------------------------------------------------------------------
#define APIT 68
#define ATT2_SMEM ((128 * APIT + 64 * APIT + 64 * APIT) * 4)   // 69632 B

__global__ __launch_bounds__(256) void attn_tc_kernel()
{
    extern __shared__ __align__(16) float sm[];
    uint32_t* Ps = (uint32_t*)sm;               // [128][68], aliases Qs
    uint32_t* Ks = Ps + 128 * APIT;             // [64][68]
    uint32_t* Vs = Ks + 64 * APIT;              // [64][68]

    const int tid  = threadIdx.x;
    const int lane = tid & 31;
    const int w    = tid >> 5;                  // 0..7
    const int qi   = blockIdx.x;                // 0..15
    const int bh   = blockIdx.y;                // 0..31

    const size_t hoff = (size_t)bh * TSEQ * HD;
    const float* Qg = g_q + hoff;
    const float* Kg = g_k + hoff;
    const float* Vg = g_v + hoff;

    // ---- load Q tile (tf32) into smem ----
#pragma unroll
    for (int u = 0; u < 8; u++) {
        const int idx = tid + u * 256;          // 0..2047
        const int r = idx >> 4, c4 = idx & 15;
        float4 v = *(const float4*)(Qg + (size_t)(qi * 128 + r) * HD + c4 * 4);
        uint4 t = make_uint4(f2tf32(v.x), f2tf32(v.y), f2tf32(v.z), f2tf32(v.w));
        *(uint4*)(Ps + r * APIT + c4 * 4) = t;
    }
    __syncthreads();

    // ---- extract Q A-fragments (kept in registers all loop) ----
    uint32_t qf[8][4];
    const int rw = w * 16 + (lane >> 2);        // local q row (first of pair)
#pragma unroll
    for (int kf = 0; kf < 8; kf++) {
        const int ka = kf * 8 + (lane & 3);
        qf[kf][0] = Ps[rw * APIT + ka];
        qf[kf][1] = Ps[(rw + 8) * APIT + ka];
        qf[kf][2] = Ps[rw * APIT + ka + 4];
        qf[kf][3] = Ps[(rw + 8) * APIT + ka + 4];
    }

    float o[8][4];
#pragma unroll
    for (int nf = 0; nf < 8; nf++)
#pragma unroll
        for (int e = 0; e < 4; e++) o[nf][e] = 0.f;
    float mrow[2] = {-INFINITY, -INFINITY};
    float lrow[2] = {0.f, 0.f};

    const int nkt = 2 * qi + 2;
    for (int kt = 0; kt < nkt; kt++) {
        __syncthreads();                        // protect Ks/Vs (and initial Qs)
        // ---- load K, V tiles (tf32, natural [key][d], pitch 68) ----
#pragma unroll
        for (int u = 0; u < 4; u++) {
            const int idx = tid + u * 256;      // 0..1023
            const int r = idx >> 4, c4 = idx & 15;
            float4 kv = *(const float4*)(Kg + (size_t)(kt * 64 + r) * HD + c4 * 4);
            float4 vv = *(const float4*)(Vg + (size_t)(kt * 64 + r) * HD + c4 * 4);
            *(uint4*)(Ks + r * APIT + c4 * 4) =
                make_uint4(f2tf32(kv.x), f2tf32(kv.y), f2tf32(kv.z), f2tf32(kv.w));
            *(uint4*)(Vs + r * APIT + c4 * 4) =
                make_uint4(f2tf32(vv.x), f2tf32(vv.y), f2tf32(vv.z), f2tf32(vv.w));
        }
        __syncthreads();

        // ---- S = Q @ K^T ----
        float s[8][4];
#pragma unroll
        for (int nf = 0; nf < 8; nf++)
#pragma unroll
            for (int e = 0; e < 4; e++) s[nf][e] = 0.f;

#pragma unroll
        for (int kf = 0; kf < 8; kf++) {
            const int ka = kf * 8 + (lane & 3);
#pragma unroll
            for (int nf = 0; nf < 8; nf++) {
                uint32_t b[2];
                const int n = nf * 8 + (lane >> 2);
                b[0] = Ks[n * APIT + ka];
                b[1] = Ks[n * APIT + ka + 4];
                mma_tf32(s[nf], qf[kf], b);
            }
        }

        // ---- scale + causal mask ----
        const bool part = (kt >= 2 * qi);
        const int qg0 = qi * 128 + rw;
#pragma unroll
        for (int nf = 0; nf < 8; nf++) {
            const int cg = kt * 64 + nf * 8 + 2 * (lane & 3);
#pragma unroll
            for (int e = 0; e < 4; e++) {
                s[nf][e] *= 0.125f;
                if (part) {
                    const int col = cg + (e & 1);
                    const int row = qg0 + (e >> 1) * 8;
                    if (col > row) s[nf][e] = -INFINITY;
                }
            }
        }

        // ---- online softmax ----
        float rm[2] = {-INFINITY, -INFINITY};
#pragma unroll
        for (int nf = 0; nf < 8; nf++) {
            rm[0] = fmaxf(rm[0], fmaxf(s[nf][0], s[nf][1]));
            rm[1] = fmaxf(rm[1], fmaxf(s[nf][2], s[nf][3]));
        }
#pragma unroll
        for (int xo = 1; xo <= 2; xo <<= 1) {
            rm[0] = fmaxf(rm[0], __shfl_xor_sync(0xFFFFFFFF, rm[0], xo));
            rm[1] = fmaxf(rm[1], __shfl_xor_sync(0xFFFFFFFF, rm[1], xo));
        }
        float cor[2], mnew[2];
#pragma unroll
        for (int e = 0; e < 2; e++) {
            mnew[e] = fmaxf(mrow[e], rm[e]);
            cor[e] = __expf(mrow[e] - mnew[e]);
            mrow[e] = mnew[e];
        }

        float rs[2] = {0.f, 0.f};
#pragma unroll
        for (int nf = 0; nf < 8; nf++) {
            float p0 = __expf(s[nf][0] - mnew[0]);
            float p1 = __expf(s[nf][1] - mnew[0]);
            float p2 = __expf(s[nf][2] - mnew[1]);
            float p3 = __expf(s[nf][3] - mnew[1]);
            rs[0] += p0 + p1;
            rs[1] += p2 + p3;
            // rescale O
            o[nf][0] *= cor[0]; o[nf][1] *= cor[0];
            o[nf][2] *= cor[1]; o[nf][3] *= cor[1];
            // store P (tf32) to warp-private smem region
            const int cb = nf * 8 + 2 * (lane & 3);
            uint32_t* p = Ps + rw * APIT + cb;
            p[0] = f2tf32(p0); p[1] = f2tf32(p1);
            uint32_t* p2v = Ps + (rw + 8) * APIT + cb;
            p2v[0] = f2tf32(p2); p2v[1] = f2tf32(p3);
        }
#pragma unroll
        for (int xo = 1; xo <= 2; xo <<= 1) {
            rs[0] += __shfl_xor_sync(0xFFFFFFFF, rs[0], xo);
            rs[1] += __shfl_xor_sync(0xFFFFFFFF, rs[1], xo);
        }
        lrow[0] = lrow[0] * cor[0] + rs[0];
        lrow[1] = lrow[1] * cor[1] + rs[1];

        __syncwarp();   // Ps region is warp-private; order STS -> LDS

        // ---- O += P @ V ----
#pragma unroll
        for (int kf = 0; kf < 8; kf++) {
            uint32_t a[4];
            const int ka = kf * 8 + (lane & 3);
            a[0] = Ps[rw * APIT + ka];
            a[1] = Ps[(rw + 8) * APIT + ka];
            a[2] = Ps[rw * APIT + ka + 4];
            a[3] = Ps[(rw + 8) * APIT + ka + 4];
#pragma unroll
            for (int nf = 0; nf < 8; nf++) {
                uint32_t b[2];
                const int d = nf * 8 + (lane >> 2);
                b[0] = Vs[(kf * 8 + (lane & 3)) * APIT + d];
                b[1] = Vs[(kf * 8 + (lane & 3) + 4) * APIT + d];
                mma_tf32(o[nf], a, b);
            }
        }
        __syncwarp();
    }

    // ---- normalize + write g_y[b][t][h*64+d] ----
    const int b = bh >> 4;
    const int h = bh & 15;
    const float inv0 = 1.0f / lrow[0];
    const float inv1 = 1.0f / lrow[1];
    const int t0 = qi * 128 + rw;
    float* yrow0 = g_y + ((size_t)b * TSEQ + t0) * CDIM + h * 64;
    float* yrow1 = g_y + ((size_t)b * TSEQ + t0 + 8) * CDIM + h * 64;
#pragma unroll
    for (int nf = 0; nf < 8; nf++) {
        const int c = nf * 8 + 2 * (lane & 3);
        *(float2*)(yrow0 + c) = make_float2(o[nf][0] * inv0, o[nf][1] * inv0);
        *(float2*)(yrow1 + c) = make_float2(o[nf][2] * inv1, o[nf][3] * inv1);
    }
}

// ---------------------------------------------------------------------------
extern "C" void kernel_launch(void* const* d_in, const int* in_sizes, int n_in,
                              void* d_out, int out_size)
{
    const float* x      = (const float*)d_in[0];
    const float* W_attn = (const float*)d_in[1];
    const float* b_attn = (const float*)d_in[2];
    const float* W_proj = (const float*)d_in[3];
    const float* b_proj = (const float*)d_in[4];
    float* out = (float*)d_out;

    static bool attr_set = false;
    if (!attr_set) {
        cudaFuncSetAttribute(attn_tc_kernel,
                             cudaFuncAttributeMaxDynamicSharedMemorySize, ATT2_SMEM);
        cudaFuncSetAttribute((const void*)tc_gemm_kernel<true, false>,
                             cudaFuncAttributeMaxDynamicSharedMemorySize, GEMM_DYN);
        cudaFuncSetAttribute((const void*)tc_gemm_kernel<false, true>,
                             cudaFuncAttributeMaxDynamicSharedMemorySize, GEMM_DYN);
        attr_set = true;
    }

    // 1) QKV GEMM (tf32 mma.sync)
    {
        dim3 grid(N3 / 128, MROWS / 128);
        tc_gemm_kernel<true, false><<<grid, 256, GEMM_DYN>>>(x, W_attn, b_attn, nullptr, N3);
    }
    // 2) Flash attention (tf32 mma.sync)
    {
        dim3 grid(TSEQ / 128, BSZ * NH);
        attn_tc_kernel<<<grid, 256, ATT2_SMEM>>>();
    }
    // 3) Projection GEMM (tf32 mma.sync), A = g_y
    {
        dim3 grid(CDIM / 128, MROWS / 128);
        tc_gemm_kernel<false, true><<<grid, 256, GEMM_DYN>>>(nullptr, W_proj, b_proj, out, CDIM);
    }
}

// round 6
// speedup vs baseline: 5.9944x; 1.3750x over previous
#include <cuda_runtime.h>
#include <math.h>
#include <stdint.h>

// Problem constants
#define BSZ   2
#define TSEQ  2048
#define NH    16
#define HD    64
#define CDIM  1024
#define N3    (3 * CDIM)
#define MROWS (BSZ * TSEQ)          // 4096

// Scratch (device globals: allocation-free per harness rules)
__device__ float g_q[(size_t)BSZ * NH * TSEQ * HD];
__device__ float g_k[(size_t)BSZ * NH * TSEQ * HD];
__device__ float g_v[(size_t)BSZ * NH * TSEQ * HD];
__device__ float g_y[(size_t)BSZ * TSEQ * CDIM];

// ---------------------------------------------------------------------------
// tf32 helpers (portable PTX, sm_80+)
// ---------------------------------------------------------------------------
__device__ __forceinline__ uint32_t f2tf32(float x) {
    uint32_t u;
    asm("cvt.rn.tf32.f32 %0, %1;" : "=r"(u) : "f"(x));
    return u;
}

__device__ __forceinline__ void mma_tf32(float* d, const uint32_t* a, const uint32_t* b) {
    asm volatile(
        "mma.sync.aligned.m16n8k8.row.col.f32.tf32.tf32.f32 "
        "{%0,%1,%2,%3}, {%4,%5,%6,%7}, {%8,%9}, {%0,%1,%2,%3};"
        : "+f"(d[0]), "+f"(d[1]), "+f"(d[2]), "+f"(d[3])
        : "r"(a[0]), "r"(a[1]), "r"(a[2]), "r"(a[3]), "r"(b[0]), "r"(b[1]));
}

// ---------------------------------------------------------------------------
// tf32 mma.sync GEMM: CTA tile 128x256, warp tile 64x64, K-tile 32,
// double-buffered smem, register prefetch.
// A smem [128][36]  (36%32=4 -> a-frag bank 4m+ka unique: conflict-free)
// B smem [32][264]  (264%32=8 -> b-frag bank 8ka+n unique: conflict-free)
// ---------------------------------------------------------------------------
#define BM 128
#define BN 256
#define BK 32
#define NCHUNK  (CDIM / BK)            // 32
#define APITCH  36
#define BPITCH  264
#define A_FL    (BM * APITCH)          // 4608
#define B_FL    (BK * BPITCH)          // 8448
#define ST_FL   (A_FL + B_FL)          // 13056
#define GEMM_DYN (2 * ST_FL * 4)       // 104448 bytes

template <bool EPI_QKV, bool A_GY>
__global__ __launch_bounds__(256)
void tc_gemm_kernel(const float* __restrict__ Ain, const float* __restrict__ W,
                    const float* __restrict__ bias, float* __restrict__ out,
                    int ldb)
{
    extern __shared__ __align__(16) float sm[];
    __shared__ float sbias[BN];

    const float* __restrict__ A = A_GY ? (const float*)g_y : Ain;

    const int tid    = threadIdx.x;
    const int lane   = tid & 31;
    const int wid    = tid >> 5;
    const int warp_m = wid & 1;            // 0..1, 64 rows each
    const int warp_n = wid >> 1;           // 0..3, 64 cols each
    const int m0 = blockIdx.y * BM;
    const int n0 = blockIdx.x * BN;

    sbias[tid] = bias[n0 + tid];

    float acc[4][8][4];
#pragma unroll
    for (int mf = 0; mf < 4; mf++)
#pragma unroll
        for (int nf = 0; nf < 8; nf++)
#pragma unroll
            for (int r = 0; r < 4; r++) acc[mf][nf][r] = 0.f;

    // ---- prologue: fill stage 0 ----
    {
        float* As = sm;
        float* Bs = sm + A_FL;
#pragma unroll
        for (int u = 0; u < 4; u++) {          // A: 128x32 floats
            const int idx = tid + u * 256;
            const int row = idx >> 3, c4 = idx & 7;
            float4 v = *(const float4*)(A + (size_t)(m0 + row) * CDIM + c4 * 4);
            uint4 t = make_uint4(f2tf32(v.x), f2tf32(v.y), f2tf32(v.z), f2tf32(v.w));
            *(uint4*)(As + row * APITCH + c4 * 4) = t;
        }
#pragma unroll
        for (int u = 0; u < 8; u++) {          // B: 32x256 floats
            const int idx = tid + u * 256;
            const int k = idx >> 6, n4 = idx & 63;
            float4 v = *(const float4*)(W + (size_t)k * ldb + n0 + n4 * 4);
            uint4 t = make_uint4(f2tf32(v.x), f2tf32(v.y), f2tf32(v.z), f2tf32(v.w));
            *(uint4*)(Bs + k * BPITCH + n4 * 4) = t;
        }
    }
    __syncthreads();

    for (int i = 0; i < NCHUNK; i++) {
        // prefetch next K-tile into registers
        float4 pa[4], pb[8];
        if (i + 1 < NCHUNK) {
            const int k0n = (i + 1) * BK;
#pragma unroll
            for (int u = 0; u < 4; u++) {
                const int idx = tid + u * 256;
                const int row = idx >> 3, c4 = idx & 7;
                pa[u] = *(const float4*)(A + (size_t)(m0 + row) * CDIM + k0n + c4 * 4);
            }
#pragma unroll
            for (int u = 0; u < 8; u++) {
                const int idx = tid + u * 256;
                const int k = idx >> 6, n4 = idx & 63;
                pb[u] = *(const float4*)(W + (size_t)(k0n + k) * ldb + n0 + n4 * 4);
            }
        }

        // compute on current stage
        {
            const uint32_t* As = (const uint32_t*)(sm + (i & 1) * ST_FL);
            const uint32_t* Bs = As + A_FL;
#pragma unroll
            for (int kk = 0; kk < BK; kk += 8) {
                uint32_t a[4][4], b[8][2];
                const int ka = kk + (lane & 3);
#pragma unroll
                for (int mf = 0; mf < 4; mf++) {
                    const int m = warp_m * 64 + mf * 16 + (lane >> 2);
                    a[mf][0] = As[m * APITCH + ka];
                    a[mf][1] = As[(m + 8) * APITCH + ka];
                    a[mf][2] = As[m * APITCH + ka + 4];
                    a[mf][3] = As[(m + 8) * APITCH + ka + 4];
                }
#pragma unroll
                for (int nf = 0; nf < 8; nf++) {
                    const int n = warp_n * 64 + nf * 8 + (lane >> 2);
                    b[nf][0] = Bs[ka * BPITCH + n];
                    b[nf][1] = Bs[(ka + 4) * BPITCH + n];
                }
#pragma unroll
                for (int mf = 0; mf < 4; mf++)
#pragma unroll
                    for (int nf = 0; nf < 8; nf++)
                        mma_tf32(acc[mf][nf], a[mf], b[nf]);
            }
        }

        // store prefetched tile into other stage
        if (i + 1 < NCHUNK) {
            float* As = sm + ((i + 1) & 1) * ST_FL;
            float* Bs = As + A_FL;
#pragma unroll
            for (int u = 0; u < 4; u++) {
                const int idx = tid + u * 256;
                const int row = idx >> 3, c4 = idx & 7;
                uint4 t = make_uint4(f2tf32(pa[u].x), f2tf32(pa[u].y),
                                     f2tf32(pa[u].z), f2tf32(pa[u].w));
                *(uint4*)(As + row * APITCH + c4 * 4) = t;
            }
#pragma unroll
            for (int u = 0; u < 8; u++) {
                const int idx = tid + u * 256;
                const int k = idx >> 6, n4 = idx & 63;
                uint4 t = make_uint4(f2tf32(pb[u].x), f2tf32(pb[u].y),
                                     f2tf32(pb[u].z), f2tf32(pb[u].w));
                *(uint4*)(Bs + k * BPITCH + n4 * 4) = t;
            }
        }
        __syncthreads();
    }

    // ---- epilogue: direct STG.64 from fragments (+bias) ----
#pragma unroll
    for (int mf = 0; mf < 4; mf++) {
        const int r0 = m0 + warp_m * 64 + mf * 16 + (lane >> 2);
#pragma unroll
        for (int nf = 0; nf < 8; nf++) {
            const int cb_loc = warp_n * 64 + nf * 8 + 2 * (lane & 3);
            const float b0 = sbias[cb_loc], b1 = sbias[cb_loc + 1];
            float2 v0 = make_float2(acc[mf][nf][0] + b0, acc[mf][nf][1] + b1);
            float2 v1 = make_float2(acc[mf][nf][2] + b0, acc[mf][nf][3] + b1);
            if (EPI_QKV) {
                const int col = n0 + cb_loc;
                const int sec = col >> 10;
                const int c   = col & (CDIM - 1);
                const int h   = c >> 6;
                const int d0  = c & (HD - 1);
                float* dst = (sec == 0) ? g_q : ((sec == 1) ? g_k : g_v);
                const int bb0 = r0 >> 11, t0 = r0 & (TSEQ - 1);
                *(float2*)(dst + (((size_t)bb0 * NH + h) * TSEQ + t0) * HD + d0) = v0;
                const int r1 = r0 + 8;
                const int bb1 = r1 >> 11, t1 = r1 & (TSEQ - 1);
                *(float2*)(dst + (((size_t)bb1 * NH + h) * TSEQ + t1) * HD + d0) = v1;
            } else {
                *(float2*)(out + (size_t)r0 * CDIM + n0 + cb_loc) = v0;
                *(float2*)(out + (size_t)(r0 + 8) * CDIM + n0 + cb_loc) = v1;
            }
        }
    }
}

// ---------------------------------------------------------------------------
// Kernel 2: causal flash attention on tf32 mma.sync.
// CTA: 128 q-rows x one (b,h). 8 warps x 16 rows. K-tile = 64 keys.
// KV double-buffered (register prefetch, one barrier per tile).
// Ps/Qs alias [128][68]; Ks [2][64][68] (68%32=4: S b-frags conflict-free);
// Vs [2][64][72] (72%32=8: PV b-frags conflict-free).
// ---------------------------------------------------------------------------
#define QPIT 68
#define KPIT 68
#define VPIT 72
#define ATT2_SMEM ((128 * QPIT + 2 * 64 * KPIT + 2 * 64 * VPIT) * 4)  // 106496 B

__global__ __launch_bounds__(256) void attn_tc_kernel()
{
    extern __shared__ __align__(16) float sm[];
    uint32_t* Ps  = (uint32_t*)sm;               // [128][68], aliases Qs
    uint32_t* Ksb = Ps + 128 * QPIT;             // [2][64][68]
    uint32_t* Vsb = Ksb + 2 * 64 * KPIT;         // [2][64][72]

    const int tid  = threadIdx.x;
    const int lane = tid & 31;
    const int w    = tid >> 5;                   // 0..7
    const int qi   = blockIdx.x;                 // 0..15
    const int bh   = blockIdx.y;                 // 0..31

    const size_t hoff = (size_t)bh * TSEQ * HD;
    const float* Qg = g_q + hoff;
    const float* Kg = g_k + hoff;
    const float* Vg = g_v + hoff;

    // ---- load Q tile (tf32) into smem ----
#pragma unroll
    for (int u = 0; u < 8; u++) {
        const int idx = tid + u * 256;
        const int r = idx >> 4, c4 = idx & 15;
        float4 v = *(const float4*)(Qg + (size_t)(qi * 128 + r) * HD + c4 * 4);
        uint4 t = make_uint4(f2tf32(v.x), f2tf32(v.y), f2tf32(v.z), f2tf32(v.w));
        *(uint4*)(Ps + r * QPIT + c4 * 4) = t;
    }
    __syncthreads();

    // ---- extract Q A-fragments (registers for whole loop) ----
    uint32_t qf[8][4];
    const int rw = w * 16 + (lane >> 2);
#pragma unroll
    for (int kf = 0; kf < 8; kf++) {
        const int ka = kf * 8 + (lane & 3);
        qf[kf][0] = Ps[rw * QPIT + ka];
        qf[kf][1] = Ps[(rw + 8) * QPIT + ka];
        qf[kf][2] = Ps[rw * QPIT + ka + 4];
        qf[kf][3] = Ps[(rw + 8) * QPIT + ka + 4];
    }

    // ---- prologue: fill KV stage 0 ----
#pragma unroll
    for (int u = 0; u < 4; u++) {
        const int idx = tid + u * 256;
        const int r = idx >> 4, c4 = idx & 15;
        float4 kv = *(const float4*)(Kg + (size_t)r * HD + c4 * 4);
        float4 vv = *(const float4*)(Vg + (size_t)r * HD + c4 * 4);
        *(uint4*)(Ksb + r * KPIT + c4 * 4) =
            make_uint4(f2tf32(kv.x), f2tf32(kv.y), f2tf32(kv.z), f2tf32(kv.w));
        *(uint4*)(Vsb + r * VPIT + c4 * 4) =
            make_uint4(f2tf32(vv.x), f2tf32(vv.y), f2tf32(vv.z), f2tf32(vv.w));
    }

    float o[8][4];
#pragma unroll
    for (int nf = 0; nf < 8; nf++)
#pragma unroll
        for (int e = 0; e < 4; e++) o[nf][e] = 0.f;
    float mrow[2] = {-INFINITY, -INFINITY};
    float lrow[2] = {0.f, 0.f};

    const int nkt = 2 * qi + 2;
    for (int kt = 0; kt < nkt; kt++) {
        // prefetch next KV tile into registers
        float4 pk[4], pv[4];
        if (kt + 1 < nkt) {
#pragma unroll
            for (int u = 0; u < 4; u++) {
                const int idx = tid + u * 256;
                const int r = idx >> 4, c4 = idx & 15;
                pk[u] = *(const float4*)(Kg + (size_t)((kt + 1) * 64 + r) * HD + c4 * 4);
                pv[u] = *(const float4*)(Vg + (size_t)((kt + 1) * 64 + r) * HD + c4 * 4);
            }
        }
        __syncthreads();   // stage kt writes visible; prior compute done
        if (kt + 1 < nkt) {
            uint32_t* Kn = Ksb + ((kt + 1) & 1) * 64 * KPIT;
            uint32_t* Vn = Vsb + ((kt + 1) & 1) * 64 * VPIT;
#pragma unroll
            for (int u = 0; u < 4; u++) {
                const int idx = tid + u * 256;
                const int r = idx >> 4, c4 = idx & 15;
                *(uint4*)(Kn + r * KPIT + c4 * 4) =
                    make_uint4(f2tf32(pk[u].x), f2tf32(pk[u].y), f2tf32(pk[u].z), f2tf32(pk[u].w));
                *(uint4*)(Vn + r * VPIT + c4 * 4) =
                    make_uint4(f2tf32(pv[u].x), f2tf32(pv[u].y), f2tf32(pv[u].z), f2tf32(pv[u].w));
            }
        }
        const uint32_t* Ks = Ksb + (kt & 1) * 64 * KPIT;
        const uint32_t* Vs = Vsb + (kt & 1) * 64 * VPIT;

        // ---- S = Q @ K^T ----
        float s[8][4];
#pragma unroll
        for (int nf = 0; nf < 8; nf++)
#pragma unroll
            for (int e = 0; e < 4; e++) s[nf][e] = 0.f;

#pragma unroll
        for (int kf = 0; kf < 8; kf++) {
            const int ka = kf * 8 + (lane & 3);
#pragma unroll
            for (int nf = 0; nf < 8; nf++) {
                uint32_t b[2];
                const int n = nf * 8 + (lane >> 2);
                b[0] = Ks[n * KPIT + ka];
                b[1] = Ks[n * KPIT + ka + 4];
                mma_tf32(s[nf], qf[kf], b);
            }
        }

        // ---- scale + causal mask ----
        const bool part = (kt >= 2 * qi);
        const int qg0 = qi * 128 + rw;
#pragma unroll
        for (int nf = 0; nf < 8; nf++) {
            const int cg = kt * 64 + nf * 8 + 2 * (lane & 3);
#pragma unroll
            for (int e = 0; e < 4; e++) {
                s[nf][e] *= 0.125f;
                if (part) {
                    const int col = cg + (e & 1);
                    const int row = qg0 + (e >> 1) * 8;
                    if (col > row) s[nf][e] = -INFINITY;
                }
            }
        }

        // ---- online softmax ----
        float rm[2] = {-INFINITY, -INFINITY};
#pragma unroll
        for (int nf = 0; nf < 8; nf++) {
            rm[0] = fmaxf(rm[0], fmaxf(s[nf][0], s[nf][1]));
            rm[1] = fmaxf(rm[1], fmaxf(s[nf][2], s[nf][3]));
        }
#pragma unroll
        for (int xo = 1; xo <= 2; xo <<= 1) {
            rm[0] = fmaxf(rm[0], __shfl_xor_sync(0xFFFFFFFF, rm[0], xo));
            rm[1] = fmaxf(rm[1], __shfl_xor_sync(0xFFFFFFFF, rm[1], xo));
        }
        float cor[2], mnew[2];
#pragma unroll
        for (int e = 0; e < 2; e++) {
            mnew[e] = fmaxf(mrow[e], rm[e]);
            cor[e] = __expf(mrow[e] - mnew[e]);
            mrow[e] = mnew[e];
        }

        float rs[2] = {0.f, 0.f};
#pragma unroll
        for (int nf = 0; nf < 8; nf++) {
            float p0 = __expf(s[nf][0] - mnew[0]);
            float p1 = __expf(s[nf][1] - mnew[0]);
            float p2 = __expf(s[nf][2] - mnew[1]);
            float p3 = __expf(s[nf][3] - mnew[1]);
            rs[0] += p0 + p1;
            rs[1] += p2 + p3;
            o[nf][0] *= cor[0]; o[nf][1] *= cor[0];
            o[nf][2] *= cor[1]; o[nf][3] *= cor[1];
            const int cb = nf * 8 + 2 * (lane & 3);
            uint32_t* p = Ps + rw * QPIT + cb;
            p[0] = f2tf32(p0); p[1] = f2tf32(p1);
            uint32_t* p2v = Ps + (rw + 8) * QPIT + cb;
            p2v[0] = f2tf32(p2); p2v[1] = f2tf32(p3);
        }
#pragma unroll
        for (int xo = 1; xo <= 2; xo <<= 1) {
            rs[0] += __shfl_xor_sync(0xFFFFFFFF, rs[0], xo);
            rs[1] += __shfl_xor_sync(0xFFFFFFFF, rs[1], xo);
        }
        lrow[0] = lrow[0] * cor[0] + rs[0];
        lrow[1] = lrow[1] * cor[1] + rs[1];

        __syncwarp();   // Ps region warp-private: order STS -> LDS

        // ---- O += P @ V ----
#pragma unroll
        for (int kf = 0; kf < 8; kf++) {
            uint32_t a[4];
            const int ka = kf * 8 + (lane & 3);
            a[0] = Ps[rw * QPIT + ka];
            a[1] = Ps[(rw + 8) * QPIT + ka];
            a[2] = Ps[rw * QPIT + ka + 4];
            a[3] = Ps[(rw + 8) * QPIT + ka + 4];
#pragma unroll
            for (int nf = 0; nf < 8; nf++) {
                uint32_t b[2];
                const int d = nf * 8 + (lane >> 2);
                b[0] = Vs[(kf * 8 + (lane & 3)) * VPIT + d];
                b[1] = Vs[(kf * 8 + (lane & 3) + 4) * VPIT + d];
                mma_tf32(o[nf], a, b);
            }
        }
        __syncwarp();
    }

    // ---- normalize + write g_y[b][t][h*64+d] ----
    const int b = bh >> 4;
    const int h = bh & 15;
    const float inv0 = 1.0f / lrow[0];
    const float inv1 = 1.0f / lrow[1];
    const int t0 = qi * 128 + rw;
    float* yrow0 = g_y + ((size_t)b * TSEQ + t0) * CDIM + h * 64;
    float* yrow1 = g_y + ((size_t)b * TSEQ + t0 + 8) * CDIM + h * 64;
#pragma unroll
    for (int nf = 0; nf < 8; nf++) {
        const int c = nf * 8 + 2 * (lane & 3);
        *(float2*)(yrow0 + c) = make_float2(o[nf][0] * inv0, o[nf][1] * inv0);
        *(float2*)(yrow1 + c) = make_float2(o[nf][2] * inv1, o[nf][3] * inv1);
    }
}

// ---------------------------------------------------------------------------
extern "C" void kernel_launch(void* const* d_in, const int* in_sizes, int n_in,
                              void* d_out, int out_size)
{
    const float* x      = (const float*)d_in[0];
    const float* W_attn = (const float*)d_in[1];
    const float* b_attn = (const float*)d_in[2];
    const float* W_proj = (const float*)d_in[3];
    const float* b_proj = (const float*)d_in[4];
    float* out = (float*)d_out;

    static bool attr_set = false;
    if (!attr_set) {
        cudaFuncSetAttribute(attn_tc_kernel,
                             cudaFuncAttributeMaxDynamicSharedMemorySize, ATT2_SMEM);
        cudaFuncSetAttribute((const void*)tc_gemm_kernel<true, false>,
                             cudaFuncAttributeMaxDynamicSharedMemorySize, GEMM_DYN);
        cudaFuncSetAttribute((const void*)tc_gemm_kernel<false, true>,
                             cudaFuncAttributeMaxDynamicSharedMemorySize, GEMM_DYN);
        attr_set = true;
    }

    // 1) QKV GEMM (tf32 mma.sync): [4096,1024] x [1024,3072]
    {
        dim3 grid(N3 / BN, MROWS / BM);
        tc_gemm_kernel<true, false><<<grid, 256, GEMM_DYN>>>(x, W_attn, b_attn, nullptr, N3);
    }
    // 2) Flash attention (tf32 mma.sync, double-buffered KV)
    {
        dim3 grid(TSEQ / 128, BSZ * NH);
        attn_tc_kernel<<<grid, 256, ATT2_SMEM>>>();
    }
    // 3) Projection GEMM (tf32 mma.sync), A = g_y
    {
        dim3 grid(CDIM / BN, MROWS / BM);
        tc_gemm_kernel<false, true><<<grid, 256, GEMM_DYN>>>(nullptr, W_proj, b_proj, out, CDIM);
    }
}